// round 17
// baseline (speedup 1.0000x reference)
#include <cuda_runtime.h>
#include <cuda_fp16.h>
#include <math.h>
#include <stdint.h>

// ---------------------------------------------------------------------------
// GWEModel on tensor cores (HMMA mma.sync m16n8k16 fp16, fp32 accumulate).
// GEMMs are C[M,N] = A[M,K] @ B[N,K]^T:
//   generator MLP (2-term): A = Ahi+Alo (fp16 split), B = fp16; C = AhB + AlB
//   layers / LM head (1-term): plain fp16 A and B
// CTA tile 128x128, BK=32, cp.async double buffering.
// rmsnorms are fused into the producing GEMM's epilogue (last-CTA-per-band).
// ---------------------------------------------------------------------------

#define D       1024
#define NLAYERS 8
#define VOCAB   32000
#define GH      256
#define NTOK    4096
#define NMAT    16
#define NROWS   65536
#define ENC_K   64
#define EPSV    1.1920929e-07f

typedef __half f16;

// ------------------------- scratch (device globals) ------------------------
__device__ float g_Xf[NTOK * D];                                 // fp32 residual
__device__ f16   g_H[NTOK * D];                                  // normed acts (fp16)
__device__ f16   g_W[(size_t)NMAT * D * D];                      // generated W (fp16)
__device__ f16   g_G0hi[(size_t)NROWS * GH], g_G0lo[(size_t)NROWS * GH];
__device__ f16   g_G1hi[(size_t)NROWS * GH], g_G1lo[(size_t)NROWS * GH];
__device__ f16   g_Ehi[(size_t)NROWS * ENC_K], g_Elo[(size_t)NROWS * ENC_K];
__device__ f16   g_W0P[GH * ENC_K];                              // gen B (fp16)
__device__ f16   g_W1[GH * GH], g_W2[GH * GH], g_W3[GH * GH];
__device__ f16   g_LM[(size_t)VOCAB * D];                        // lm head (fp16)
__device__ int   g_cnt[512];                                     // band counters

// ------------------------------- PTX helpers -------------------------------
__device__ __forceinline__ uint32_t smem_u32(const void* p) {
    uint32_t a;
    asm("{ .reg .u64 t; cvta.to.shared.u64 t, %1; cvt.u32.u64 %0, t; }"
        : "=r"(a) : "l"(p));
    return a;
}

__device__ __forceinline__ void ldmx4(uint32_t* r, uint32_t addr) {
    asm volatile("ldmatrix.sync.aligned.m8n8.x4.shared.b16 {%0,%1,%2,%3}, [%4];"
                 : "=r"(r[0]), "=r"(r[1]), "=r"(r[2]), "=r"(r[3]) : "r"(addr));
}

__device__ __forceinline__ void mma16816(float* c, const uint32_t* a,
                                         uint32_t b0, uint32_t b1) {
    asm volatile(
        "mma.sync.aligned.m16n8k16.row.col.f32.f16.f16.f32 "
        "{%0,%1,%2,%3}, {%4,%5,%6,%7}, {%8,%9}, {%0,%1,%2,%3};"
        : "+f"(c[0]), "+f"(c[1]), "+f"(c[2]), "+f"(c[3])
        : "r"(a[0]), "r"(a[1]), "r"(a[2]), "r"(a[3]), "r"(b0), "r"(b1));
}

__device__ __forceinline__ void cp16(uint32_t saddr, const void* gaddr) {
    asm volatile("cp.async.cg.shared.global [%0], [%1], 16;"
                 :: "r"(saddr), "l"(gaddr) : "memory");
}
#define CP_COMMIT() asm volatile("cp.async.commit_group;" ::: "memory")
#define CP_WAIT(N)  asm volatile("cp.async.wait_group %0;" :: "n"(N) : "memory")

// --------------------------- split/misc helpers ----------------------------
__device__ __forceinline__ void split1(float v, f16& h, f16& l) {
    h = __float2half_rn(v);
    l = __float2half_rn(v - __half2float(h));
}

__device__ __forceinline__ void store_split2(f16* ph, f16* pl,
                                             float v0, float v1) {
    f16 h0, l0, h1, l1;
    split1(v0, h0, l0); split1(v1, h1, l1);
    __half2 hh; hh.x = h0; hh.y = h1;
    __half2 ll; ll.x = l0; ll.y = l1;
    *(__half2*)ph = hh;
    *(__half2*)pl = ll;
}

__device__ __forceinline__ float siluf(float v) {
    return v / (1.0f + __expf(-v));
}

// ------------------------------ tiny kernels -------------------------------
// counter zeroing + w0 pad + w1/w2/w3 fp16 conversion, one grid-stride kernel
__global__ void k_prep(const float* __restrict__ w0, const float* __restrict__ w1,
                       const float* __restrict__ w2, const float* __restrict__ w3) {
    const int total = 512 + GH * ENC_K + 3 * GH * GH;
    for (int i = blockIdx.x * blockDim.x + threadIdx.x; i < total;
         i += gridDim.x * blockDim.x) {
        int j = i;
        if (j < 512) { g_cnt[j] = 0; continue; }
        j -= 512;
        if (j < GH * ENC_K) {
            int f = j & 63;
            g_W0P[j] = __float2half_rn((f < 52) ? w0[(j >> 6) * 52 + f] : 0.0f);
            continue;
        }
        j -= GH * ENC_K;
        if (j < GH * GH) { g_W1[j] = __float2half_rn(w1[j]); continue; }
        j -= GH * GH;
        if (j < GH * GH) { g_W2[j] = __float2half_rn(w2[j]); continue; }
        j -= GH * GH;
        g_W3[j] = __float2half_rn(w3[j]);
    }
}

__global__ void k_cvt(const float* __restrict__ s, f16* __restrict__ d, int n) {
    int i = blockIdx.x * blockDim.x + threadIdx.x;
    if (i < n) d[i] = __float2half_rn(s[i]);
}

__global__ void k_encode() {
    int idx = blockIdx.x * blockDim.x + threadIdx.x;
    if (idx >= NROWS * ENC_K) return;
    int row = idx >> 6;
    int f   = idx & 63;
    float val = 0.0f;
    if (f < 52) {
        int   mat = row >> 12;
        int   blk = row & 4095;
        float c0  = (float)(mat >> 1) * (1.0f / 7.0f);
        float c1  = (float)(blk >> 6) * (1.0f / 63.0f);
        float c2  = (float)(blk & 63) * (1.0f / 63.0f);
        float c3  = (mat & 1) ? 0.5f : 0.0f;
        float coords[4] = {c0, c1, c2, c3};
        if (f < 4) {
            val = coords[f];
        } else {
            int   q = f - 4;
            int   g = q >> 3;
            int   r = q & 7;
            float a = (float)(1 << g) * 3.14159265358979f * coords[r & 3];
            val = (r >= 4) ? cosf(a) : sinf(a);
        }
    }
    f16 h, l; split1(val, h, l);
    g_Ehi[idx] = h; g_Elo[idx] = l;
}

// embed gather + first rmsnorm fused (block owns a full token row)
__global__ void k_gather_norm(const int* __restrict__ tok,
                              const float* __restrict__ emb,
                              const float* __restrict__ nw) {
    int t   = threadIdx.x;   // 256
    int row = blockIdx.x;
    int tk  = tok[row];
    float4 a = ((const float4*)(emb + (size_t)tk * D))[t];
    ((float4*)(g_Xf + (size_t)row * D))[t] = a;
    float s = a.x * a.x + a.y * a.y + a.z * a.z + a.w * a.w;
    #pragma unroll
    for (int o = 16; o > 0; o >>= 1) s += __shfl_xor_sync(0xffffffffu, s, o);
    __shared__ float sm[8];
    if ((t & 31) == 0) sm[t >> 5] = s;
    __syncthreads();
    float tot = 0.0f;
    #pragma unroll
    for (int i = 0; i < 8; i++) tot += sm[i];
    float inv = rsqrtf(tot * (1.0f / 1024.0f) + EPSV);
    float4 wv = ((const float4*)nw)[t];
    __half2 o0, o1;
    o0.x = __float2half_rn(a.x * inv * wv.x);
    o0.y = __float2half_rn(a.y * inv * wv.y);
    o1.x = __float2half_rn(a.z * inv * wv.z);
    o1.y = __float2half_rn(a.w * inv * wv.w);
    *(__half2*)(g_H + (size_t)row * D + t * 4)     = o0;
    *(__half2*)(g_H + (size_t)row * D + t * 4 + 2) = o1;
}

// ------------------------- HMMA split-fp16 GEMM -----------------------------
// grid.x = M/128 (fast axis -> B-tile reuse in L2), grid.y = N/128.
// 256 threads = 8 warps in 2(M) x 4(N); warp tile 64x32; BK=32, 2 stages.
// NORM: last CTA per 128-row band recomputes rmsnorm of x into Hout.
enum { EPI_STORE = 0, EPI_SILU = 1, EPI_GENW = 2, EPI_RESID = 3, EPI_RESID_SILU = 4 };

#define LDB        80
#define MAT_BYTES  10240         // 128 * 80

template <int EPI, bool ASPLIT, bool NORM>
__global__ void __launch_bounds__(256, 2)
k_gemm(const f16* __restrict__ Ahi, const f16* __restrict__ Alo,
       const f16* __restrict__ B,
       const float* __restrict__ bias,
       float* __restrict__ outF,
       f16* __restrict__ outHi, f16* __restrict__ outLo,
       const float* __restrict__ nw, f16* __restrict__ Hout,
       int* __restrict__ cnt,
       int M, int N, int K) {
    constexpr int NA    = ASPLIT ? 2 : 1;
    constexpr int NMATS = NA + 1;
    constexpr uint32_t BOFF  = (uint32_t)NA * MAT_BYTES;
    constexpr uint32_t STAGE = (uint32_t)NMATS * MAT_BYTES;
    extern __shared__ char smem[];
    const uint32_t sb   = smem_u32(smem);
    const int tid  = threadIdx.x;
    const int lane = tid & 31;
    const int wid  = tid >> 5;
    const int wm   = wid >> 2;          // 0..1
    const int wn   = wid & 3;           // 0..3
    const int bm   = blockIdx.x * 128;
    const int bn   = blockIdx.y * 128;

    float acc[4][4][4];
    #pragma unroll
    for (int i = 0; i < 4; i++)
        #pragma unroll
        for (int j = 0; j < 4; j++)
            #pragma unroll
            for (int q = 0; q < 4; q++) acc[i][j][q] = 0.0f;

    const uint32_t a_off = (uint32_t)(lane & 15) * LDB + (uint32_t)(lane >> 4) * 16;
    const uint32_t b_off = (uint32_t)((lane & 7) + ((lane >> 4) & 1) * 8) * LDB
                         + (uint32_t)((lane >> 3) & 1) * 16;

    const int nch = K >> 5;

    auto load_stage = [&](int ic, int buf) {
        const int k0 = ic << 5;
        const uint32_t sbase = sb + buf * STAGE;
        #pragma unroll
        for (int it = 0; it < NMATS * 2; it++) {
            int u   = tid + it * 256;
            int seg = u >> 2;
            int c   = u & 3;
            int mat = seg >> 7;
            int rl  = seg & 127;
            const f16* src;
            if (mat == 0)                 src = Ahi + (size_t)(bm + rl) * K;
            else if (ASPLIT && mat == 1)  src = Alo + (size_t)(bm + rl) * K;
            else                          src = B   + (size_t)(bn + rl) * K;
            cp16(sbase + (uint32_t)mat * MAT_BYTES + (uint32_t)rl * LDB
                 + (uint32_t)c * 16, src + k0 + c * 8);
        }
        CP_COMMIT();
    };

    auto compute = [&](int buf) {
        const uint32_t base = sb + buf * STAGE;
        #pragma unroll
        for (int ks = 0; ks < 2; ks++) {
            uint32_t ah[4][4], al[4][4], bh[2][4];
            #pragma unroll
            for (int mt = 0; mt < 4; mt++) {
                uint32_t t0 = (uint32_t)(wm * 64 + mt * 16) * LDB + (uint32_t)ks * 32;
                ldmx4(ah[mt], base + t0 + a_off);
                if (ASPLIT) ldmx4(al[mt], base + MAT_BYTES + t0 + a_off);
            }
            #pragma unroll
            for (int g = 0; g < 2; g++) {
                uint32_t t0 = (uint32_t)(wn * 32 + g * 16) * LDB + (uint32_t)ks * 32;
                ldmx4(bh[g], base + BOFF + t0 + b_off);
            }
            #pragma unroll
            for (int mt = 0; mt < 4; mt++)
                #pragma unroll
                for (int nt = 0; nt < 4; nt++) {
                    const int g = nt >> 1, h = (nt & 1) * 2;
                    mma16816(acc[mt][nt], ah[mt], bh[g][h], bh[g][h + 1]);
                    if (ASPLIT)
                        mma16816(acc[mt][nt], al[mt], bh[g][h], bh[g][h + 1]);
                }
        }
    };

    load_stage(0, 0);
    if (nch > 1) load_stage(1, 1);
    for (int ic = 0; ic < nch; ic++) {
        if (ic + 1 < nch) { CP_WAIT(1); } else { CP_WAIT(0); }
        __syncthreads();
        compute(ic & 1);
        __syncthreads();
        if (ic + 2 < nch) load_stage(ic + 2, ic & 1);
    }

    // ------------------------------ epilogue --------------------------------
    #pragma unroll
    for (int mt = 0; mt < 4; mt++) {
        #pragma unroll
        for (int nt = 0; nt < 4; nt++) {
            const int n0 = bn + wn * 32 + nt * 8 + (lane & 3) * 2;
            #pragma unroll
            for (int half_ = 0; half_ < 2; half_++) {
                const int m = bm + wm * 64 + mt * 16 + (lane >> 2) + half_ * 8;
                float v0 = acc[mt][nt][half_ * 2 + 0];
                float v1 = acc[mt][nt][half_ * 2 + 1];
                if (EPI == EPI_STORE) {
                    *(float2*)&outF[(size_t)m * N + n0] = make_float2(v0, v1);
                } else if (EPI == EPI_SILU) {
                    const float2 bb = *(const float2*)&bias[n0];
                    store_split2(outHi + (size_t)m * N + n0,
                                 outLo + (size_t)m * N + n0,
                                 siluf(v0 + bb.x), siluf(v1 + bb.y));
                } else if (EPI == EPI_GENW) {
                    const float2 bb = *(const float2*)&bias[n0];
                    int mat = m >> 12, rb_ = (m >> 6) & 63, cb_ = m & 63;
                    int ii = n0 >> 4, jj = n0 & 15;
                    size_t off = (size_t)mat * D * D + (size_t)(rb_ * 16 + ii) * D
                               + (size_t)(cb_ * 16 + jj);
                    __half2 wv;
                    wv.x = __float2half_rn(v0 + bb.x);
                    wv.y = __float2half_rn(v1 + bb.y);
                    *(__half2*)&outHi[off] = wv;
                } else if (EPI == EPI_RESID) {
                    float2* p = (float2*)&outF[(size_t)m * N + n0];
                    float2 c = *p;
                    *p = make_float2(c.x + 0.1f * v0, c.y + 0.1f * v1);
                } else { // EPI_RESID_SILU
                    float2* p = (float2*)&outF[(size_t)m * N + n0];
                    float2 c = *p;
                    *p = make_float2(c.x + 0.1f * siluf(v0), c.y + 0.1f * siluf(v1));
                }
            }
        }
    }

    // -------------------- fused rmsnorm (last CTA per band) -----------------
    if (NORM) {
        __threadfence();
        __syncthreads();
        __shared__ int s_last;
        if (tid == 0) {
            int old = atomicAdd(&cnt[blockIdx.x], 1);
            s_last = (old == (int)gridDim.y - 1) ? 1 : 0;
        }
        __syncthreads();
        if (s_last) {
            __threadfence();
            // warp wid handles rows {bm + wid + 8*rr}, rr = 0..15
            #pragma unroll 1
            for (int rr = 0; rr < 16; rr++) {
                const int row = bm + rr * 8 + wid;
                const float4* xr = (const float4*)(outF + (size_t)row * N);
                float s = 0.0f;
                #pragma unroll
                for (int c = 0; c < 8; c++) {
                    float4 v = __ldcg(xr + lane + c * 32);
                    s += v.x * v.x + v.y * v.y + v.z * v.z + v.w * v.w;
                }
                #pragma unroll
                for (int o = 16; o > 0; o >>= 1)
                    s += __shfl_xor_sync(0xffffffffu, s, o);
                float inv = rsqrtf(s * (1.0f / 1024.0f) + EPSV);
                #pragma unroll
                for (int c = 0; c < 8; c++) {
                    float4 v  = __ldcg(xr + lane + c * 32);
                    float4 wv = ((const float4*)nw)[lane + c * 32];
                    __half2 h0, h1;
                    h0.x = __float2half_rn(v.x * inv * wv.x);
                    h0.y = __float2half_rn(v.y * inv * wv.y);
                    h1.x = __float2half_rn(v.z * inv * wv.z);
                    h1.y = __float2half_rn(v.w * inv * wv.w);
                    size_t o2 = (size_t)row * N + ((size_t)lane + c * 32) * 4;
                    *(__half2*)(Hout + o2)     = h0;
                    *(__half2*)(Hout + o2 + 2) = h1;
                }
            }
        }
    }
}

// --------------------------------- driver -----------------------------------
extern "C" void kernel_launch(void* const* d_in, const int* in_sizes, int n_in,
                              void* d_out, int out_size) {
    const int*   tokens = (const int*)d_in[0];
    const float* embed  = (const float*)d_in[1];
    const float* lmhead = (const float*)d_in[2];
    const float* finw   = (const float*)d_in[3];
    const float* n1w    = (const float*)d_in[4];
    const float* n2w    = (const float*)d_in[5];
    const float* w0     = (const float*)d_in[6];
    const float* b0     = (const float*)d_in[7];
    const float* w1     = (const float*)d_in[8];
    const float* b1     = (const float*)d_in[9];
    const float* w2     = (const float*)d_in[10];
    const float* b2     = (const float*)d_in[11];
    const float* w3     = (const float*)d_in[12];
    const float* b3     = (const float*)d_in[13];
    float* out = (float*)d_out;

    float *pXf;
    f16 *pH, *pW, *pG0hi, *pG0lo, *pG1hi, *pG1lo, *pEhi, *pElo;
    f16 *pW0P, *pW1, *pW2, *pW3, *pLM;
    int *pCnt;
    cudaGetSymbolAddress((void**)&pXf,   g_Xf);
    cudaGetSymbolAddress((void**)&pH,    g_H);
    cudaGetSymbolAddress((void**)&pW,    g_W);
    cudaGetSymbolAddress((void**)&pG0hi, g_G0hi);
    cudaGetSymbolAddress((void**)&pG0lo, g_G0lo);
    cudaGetSymbolAddress((void**)&pG1hi, g_G1hi);
    cudaGetSymbolAddress((void**)&pG1lo, g_G1lo);
    cudaGetSymbolAddress((void**)&pEhi,  g_Ehi);
    cudaGetSymbolAddress((void**)&pElo,  g_Elo);
    cudaGetSymbolAddress((void**)&pW0P,  g_W0P);
    cudaGetSymbolAddress((void**)&pW1,   g_W1);
    cudaGetSymbolAddress((void**)&pW2,   g_W2);
    cudaGetSymbolAddress((void**)&pW3,   g_W3);
    cudaGetSymbolAddress((void**)&pLM,   g_LM);
    cudaGetSymbolAddress((void**)&pCnt,  g_cnt);

    const int SM2 = 2 * 2 * MAT_BYTES;   // 40960  (1-term)
    const int SM3 = 2 * 3 * MAT_BYTES;   // 61440  (2-term)
    cudaFuncSetAttribute((const void*)k_gemm<EPI_STORE, false, false>,     cudaFuncAttributeMaxDynamicSharedMemorySize, SM2);
    cudaFuncSetAttribute((const void*)k_gemm<EPI_RESID, false, true>,      cudaFuncAttributeMaxDynamicSharedMemorySize, SM2);
    cudaFuncSetAttribute((const void*)k_gemm<EPI_RESID_SILU, false, true>, cudaFuncAttributeMaxDynamicSharedMemorySize, SM2);
    cudaFuncSetAttribute((const void*)k_gemm<EPI_SILU, true, false>,       cudaFuncAttributeMaxDynamicSharedMemorySize, SM3);
    cudaFuncSetAttribute((const void*)k_gemm<EPI_GENW, true, false>,       cudaFuncAttributeMaxDynamicSharedMemorySize, SM3);

    // --- prep: counters + generator weights, lm head cvt, encoding, gather ---
    k_prep<<<833, 256>>>(w0, w1, w2, w3);
    k_cvt<<<(VOCAB * D + 255) / 256, 256>>>(lmhead, pLM, VOCAB * D);
    k_encode<<<(NROWS * ENC_K + 255) / 256, 256>>>();
    k_gather_norm<<<NTOK, 256>>>(tokens, embed, n1w);   // fused first norm

    // --- generate all 16 weight matrices (batched coord-MLP, 2-term) ---
    dim3 gg(NROWS / 128, GH / 128);   // (512, 2)
    k_gemm<EPI_SILU, true, false><<<gg, 256, SM3>>>(
        pEhi, pElo, pW0P, b0, nullptr, pG0hi, pG0lo,
        nullptr, nullptr, nullptr, NROWS, GH, ENC_K);
    k_gemm<EPI_SILU, true, false><<<gg, 256, SM3>>>(
        pG0hi, pG0lo, pW1, b1, nullptr, pG1hi, pG1lo,
        nullptr, nullptr, nullptr, NROWS, GH, GH);
    k_gemm<EPI_SILU, true, false><<<gg, 256, SM3>>>(
        pG1hi, pG1lo, pW2, b2, nullptr, pG0hi, pG0lo,
        nullptr, nullptr, nullptr, NROWS, GH, GH);
    k_gemm<EPI_GENW, true, false><<<gg, 256, SM3>>>(
        pG0hi, pG0lo, pW3, b3, nullptr, pW, nullptr,
        nullptr, nullptr, nullptr, NROWS, GH, GH);

    // --- 8 transformer layers (1-term fp16, fused norms) ---
    dim3 gl(NTOK / 128, D / 128);     // (32, 8)
    for (int li = 0; li < NLAYERS; li++) {
        k_gemm<EPI_RESID, false, true><<<gl, 256, SM2>>>(
            pH, nullptr, pW + (size_t)(2 * li) * D * D, nullptr,
            pXf, nullptr, nullptr,
            n2w + (size_t)li * D, pH, pCnt + (2 * li) * 32,
            NTOK, D, D);
        const float* nxt = (li + 1 < NLAYERS) ? (n1w + (size_t)(li + 1) * D) : finw;
        k_gemm<EPI_RESID_SILU, false, true><<<gl, 256, SM2>>>(
            pH, nullptr, pW + (size_t)(2 * li + 1) * D * D, nullptr,
            pXf, nullptr, nullptr,
            nxt, pH, pCnt + (2 * li + 1) * 32,
            NTOK, D, D);
    }

    // --- LM head (1-term fp16) ---
    dim3 gf(NTOK / 128, VOCAB / 128); // (32, 250)
    k_gemm<EPI_STORE, false, false><<<gf, 256, SM2>>>(
        pH, nullptr, pLM, nullptr,
        out, nullptr, nullptr,
        nullptr, nullptr, nullptr,
        NTOK, VOCAB, D);
}